// round 1
// baseline (speedup 1.0000x reference)
#include <cuda_runtime.h>
#include <cstddef>

#define NAN_ 0
#define N_NODES 50000
#define NC 128
#define NE 800000
#define NS 8
#define NH 64
#define NB_ 8   // NBASES
#define LN_EPS 1e-5f

// ---------------- scratch (device globals; no allocation) ----------------
__device__ int   g_off [3][N_NODES + 1];
__device__ int   g_pos [3][N_NODES];       // doubles as degree histogram
__device__ int   g_srcs[3][NE];
__device__ float g_mid_a[(size_t)N_NODES * 256];
__device__ float g_mid_b[(size_t)N_NODES * NC];
__device__ float g_raw_a[(size_t)N_NODES * NC];
__device__ float g_raw_b[(size_t)N_NODES * NC];
__device__ float g_xa   [(size_t)N_NODES * NC];
__device__ float g_xb   [(size_t)N_NODES * NC];
__device__ float g_Wab [2][NC * NC];
__device__ float g_Wcat[2][NC * 256];   // [j][0:128]=W_ba  [j][128:256]=W_aa
__device__ float g_coeff[3][NB_];       // 0: ab, 1: ba, 2: aa

// ---------------- CSR build ----------------
__global__ void zero_deg_kernel() {
    int i = blockIdx.x * blockDim.x + threadIdx.x;
    if (i < 3 * N_NODES) ((int*)g_pos)[i] = 0;
}

__global__ void hist_kernel(const int* __restrict__ edge, int t) {
    for (int i = blockIdx.x * blockDim.x + threadIdx.x; i < NE; i += gridDim.x * blockDim.x)
        atomicAdd(&g_pos[t][edge[NE + i]], 1);
}

__global__ void scan_kernel() {
    int t = blockIdx.x;                    // one block per edge type
    int* deg = g_pos[t];
    int* off = g_off[t];
    __shared__ int sh[1024];
    __shared__ int carry;
    if (threadIdx.x == 0) carry = 0;
    __syncthreads();
    for (int base = 0; base < N_NODES; base += 1024) {
        int i = base + threadIdx.x;
        int v = (i < N_NODES) ? deg[i] : 0;
        sh[threadIdx.x] = v;
        __syncthreads();
        for (int d = 1; d < 1024; d <<= 1) {
            int add = (threadIdx.x >= d) ? sh[threadIdx.x - d] : 0;
            __syncthreads();
            sh[threadIdx.x] += add;
            __syncthreads();
        }
        int incl = sh[threadIdx.x];
        int excl = incl - v;
        int c = carry;
        if (i < N_NODES) { off[i] = c + excl; deg[i] = c + excl; }  // pos := off
        __syncthreads();
        if (threadIdx.x == 0) carry = c + sh[1023];
        __syncthreads();
    }
    if (threadIdx.x == 0) off[N_NODES] = carry;
}

__global__ void fill_kernel(const int* __restrict__ edge, int t) {
    for (int i = blockIdx.x * blockDim.x + threadIdx.x; i < NE; i += gridDim.x * blockDim.x) {
        int s = edge[i], d = edge[NE + i];
        int p = atomicAdd(&g_pos[t][d], 1);
        g_srcs[t][p] = s;
    }
}

// ---------------- schema GCN + dynamic coefficients (1 block, 512 thr) ----------------
__global__ void schema_kernel(const float* __restrict__ schema_x, const int* __restrict__ sei,
                              const float* __restrict__ pre_W, const float* __restrict__ pre_b,
                              const float* __restrict__ gcn_W, const float* __restrict__ gcn_b,
                              const float* __restrict__ coeff_W, const float* __restrict__ coeff_b,
                              float* __restrict__ out_sf, float* __restrict__ out_ori) {
    __shared__ float h [NS][NH];
    __shared__ float xw[NS][NH];
    __shared__ float sf[NS][NH];
    __shared__ float dinv[NS];
    int tid = threadIdx.x;              // 512 = 8*64
    int s = tid / NH, j = tid % NH;

    float acc = pre_b[j];
    for (int i = 0; i < NH; i++) acc += schema_x[s * NH + i] * pre_W[j * NH + i];
    h[s][j] = acc;
    out_ori[s * NH + j] = acc;
    __syncthreads();

    float xacc = 0.f;
    for (int k = 0; k < NH; k++) xacc += h[s][k] * gcn_W[j * NH + k];
    xw[s][j] = xacc;
    if (tid < NS) {
        float d = 1.0f;                  // self loop
        for (int e = 0; e < 24; e++) if (sei[24 + e] == tid) d += 1.0f;
        dinv[tid] = rsqrtf(fmaxf(d, 1e-12f));
    }
    __syncthreads();

    float o = gcn_b[j] + dinv[s] * dinv[s] * xw[s][j];
    for (int e = 0; e < 24; e++) {
        int es = sei[e], ed = sei[24 + e];
        if (ed == s) o += dinv[es] * dinv[s] * xw[es][j];
    }
    o = fmaxf(o, 0.f);
    sf[s][j] = o;
    out_sf[s * NH + j] = o;
    __syncthreads();

    if (tid < 3 * NB_) {
        int t = tid / NB_, i = tid % NB_;
        int ssrc = (t == 1) ? 1 : 0;     // ab:(0,1) ba:(1,0) aa:(0,0)
        int sdst = (t == 0) ? 1 : 0;
        float c = coeff_b[i];
        for (int k = 0; k < NH; k++) c += sf[ssrc][k] * coeff_W[i * 128 + k];
        for (int k = 0; k < NH; k++) c += sf[sdst][k] * coeff_W[i * 128 + 64 + k];
        g_coeff[t][i] = c;
    }
}

__global__ void buildW_kernel(const float* __restrict__ bases) {
    int id = blockIdx.x * blockDim.x + threadIdx.x;
    if (id >= 2 * NC * NC) return;
    int l = id / (NC * NC);
    int jk = id % (NC * NC);
    int j = jk / NC, k = jk % NC;
    float wab = 0.f, wba = 0.f, waa = 0.f;
#pragma unroll
    for (int i = 0; i < NB_; i++) {
        float b = bases[(size_t)l * NB_ * NC * NC + (size_t)i * NC * NC + jk];
        wab += g_coeff[0][i] * b;
        wba += g_coeff[1][i] * b;
        waa += g_coeff[2][i] * b;
    }
    g_Wab[l][jk] = wab;
    g_Wcat[l][j * 256 + k] = wba;
    g_Wcat[l][j * 256 + 128 + k] = waa;
}

// ---------------- aggregation: warp per destination node ----------------
__global__ void agg_kernel(const float* __restrict__ xsrc, const float* __restrict__ xdst,
                           int t, float* __restrict__ mid, int stride, int col0) {
    int g = blockIdx.x * blockDim.x + threadIdx.x;
    int node = g >> 5, lane = g & 31;
    if (node >= N_NODES) return;
    const int* off = g_off[t];
    const int* srcs = g_srcs[t];
    int beg = off[node], end = off[node + 1];
    int col = lane * 4;
    float4 a0 = make_float4(0, 0, 0, 0), a1 = a0;
    int e = beg;
    for (; e + 2 <= end; e += 2) {
        int s0 = srcs[e], s1 = srcs[e + 1];
        float4 v0 = *(const float4*)(xsrc + (size_t)s0 * NC + col);
        float4 v1 = *(const float4*)(xsrc + (size_t)s1 * NC + col);
        a0.x += v0.x; a0.y += v0.y; a0.z += v0.z; a0.w += v0.w;
        a1.x += v1.x; a1.y += v1.y; a1.z += v1.z; a1.w += v1.w;
    }
    if (e < end) {
        int s0 = srcs[e];
        float4 v0 = *(const float4*)(xsrc + (size_t)s0 * NC + col);
        a0.x += v0.x; a0.y += v0.y; a0.z += v0.z; a0.w += v0.w;
    }
    float inv = 1.0f / fmaxf((float)(end - beg), 1.0f);
    float4 xd = *(const float4*)(xdst + (size_t)node * NC + col);
    float4 r;
    r.x = (a0.x + a1.x) * inv + xd.x;
    r.y = (a0.y + a1.y) * inv + xd.y;
    r.z = (a0.z + a1.z) * inv + xd.z;
    r.w = (a0.w + a1.w) * inv + xd.w;
    *(float4*)(mid + (size_t)node * stride + col0 + col) = r;
}

// ---------------- GEMM: out[M,128] = A[M,K] @ W[128,K]^T ----------------
template <int K>
__global__ void gemm_kernel(const float* __restrict__ A, const float* __restrict__ W,
                            float* __restrict__ out) {
    constexpr int KC = 16;
    __shared__ __align__(16) float At[KC][132];
    __shared__ __align__(16) float Wt[KC][132];
    int tid = threadIdx.x;               // 256
    int tx = tid & 15, ty = tid >> 4;    // 16x16 threads, 8x8 micro tile
    int row0 = blockIdx.x * 128;

    float acc[8][8];
#pragma unroll
    for (int i = 0; i < 8; i++)
#pragma unroll
        for (int j = 0; j < 8; j++) acc[i][j] = 0.f;

    for (int kc = 0; kc < K; kc += KC) {
#pragma unroll
        for (int it = 0; it < 2; it++) {
            int idx = tid + it * 256;    // 0..511
            int r = idx >> 2;
            int kk = (idx & 3) * 4;
            float4 v = make_float4(0, 0, 0, 0);
            if (row0 + r < N_NODES)
                v = *(const float4*)(A + (size_t)(row0 + r) * K + kc + kk);
            At[kk + 0][r] = v.x; At[kk + 1][r] = v.y; At[kk + 2][r] = v.z; At[kk + 3][r] = v.w;
            int j = r;
            float4 w = *(const float4*)(W + (size_t)j * K + kc + kk);
            Wt[kk + 0][j] = w.x; Wt[kk + 1][j] = w.y; Wt[kk + 2][j] = w.z; Wt[kk + 3][j] = w.w;
        }
        __syncthreads();
#pragma unroll
        for (int k = 0; k < KC; k++) {
            float4 a0 = *(const float4*)&At[k][ty * 8];
            float4 a1 = *(const float4*)&At[k][ty * 8 + 4];
            float4 w0 = *(const float4*)&Wt[k][tx * 8];
            float4 w1 = *(const float4*)&Wt[k][tx * 8 + 4];
            float a[8] = {a0.x, a0.y, a0.z, a0.w, a1.x, a1.y, a1.z, a1.w};
            float w[8] = {w0.x, w0.y, w0.z, w0.w, w1.x, w1.y, w1.z, w1.w};
#pragma unroll
            for (int i = 0; i < 8; i++)
#pragma unroll
                for (int j = 0; j < 8; j++) acc[i][j] += a[i] * w[j];
        }
        __syncthreads();
    }
#pragma unroll
    for (int i = 0; i < 8; i++) {
        int r = row0 + ty * 8 + i;
        if (r < N_NODES) {
            float4 o0 = make_float4(acc[i][0], acc[i][1], acc[i][2], acc[i][3]);
            float4 o1 = make_float4(acc[i][4], acc[i][5], acc[i][6], acc[i][7]);
            *(float4*)(out + (size_t)r * NC + tx * 8) = o0;
            *(float4*)(out + (size_t)r * NC + tx * 8 + 4) = o1;
        }
    }
}

// ---------------- bias + LayerNorm + ReLU (warp per row) ----------------
__global__ void ln_kernel(const float* __restrict__ raw, const float* __restrict__ b1,
                          const float* __restrict__ b2, const float* __restrict__ lw,
                          const float* __restrict__ lb, float* __restrict__ xout) {
    int g = blockIdx.x * blockDim.x + threadIdx.x;
    int node = g >> 5, lane = g & 31;
    if (node >= N_NODES) return;
    int col = lane * 4;
    float4 v = *(const float4*)(raw + (size_t)node * NC + col);
    float4 bb = *(const float4*)(b1 + col);
    v.x += bb.x; v.y += bb.y; v.z += bb.z; v.w += bb.w;
    if (b2) {
        float4 b2v = *(const float4*)(b2 + col);
        v.x += b2v.x; v.y += b2v.y; v.z += b2v.z; v.w += b2v.w;
    }
    float s = v.x + v.y + v.z + v.w;
#pragma unroll
    for (int o = 16; o > 0; o >>= 1) s += __shfl_xor_sync(0xffffffffu, s, o);
    float mu = s * (1.0f / NC);
    float dx = v.x - mu, dy = v.y - mu, dz = v.z - mu, dw = v.w - mu;
    float q = dx * dx + dy * dy + dz * dz + dw * dw;
#pragma unroll
    for (int o = 16; o > 0; o >>= 1) q += __shfl_xor_sync(0xffffffffu, q, o);
    float rs = rsqrtf(q * (1.0f / NC) + LN_EPS);
    float4 w = *(const float4*)(lw + col);
    float4 b = *(const float4*)(lb + col);
    float4 y;
    y.x = fmaxf(dx * rs * w.x + b.x, 0.f);
    y.y = fmaxf(dy * rs * w.y + b.y, 0.f);
    y.z = fmaxf(dz * rs * w.z + b.z, 0.f);
    y.w = fmaxf(dw * rs * w.w + b.w, 0.f);
    *(float4*)(xout + (size_t)node * NC + col) = y;
}

// ---------------- launch ----------------
extern "C" void kernel_launch(void* const* d_in, const int* in_sizes, int n_in,
                              void* d_out, int out_size) {
    (void)in_sizes; (void)n_in; (void)out_size;
    const float* x_a      = (const float*)d_in[0];
    const float* x_b      = (const float*)d_in[1];
    const float* schema_x = (const float*)d_in[2];
    const int*   e_ab     = (const int*)d_in[3];
    const int*   e_ba     = (const int*)d_in[4];
    const int*   e_aa     = (const int*)d_in[5];
    const int*   sei      = (const int*)d_in[6];
    const float* pre_W    = (const float*)d_in[7];
    const float* pre_b    = (const float*)d_in[8];
    const float* gcn_W    = (const float*)d_in[9];
    const float* gcn_b    = (const float*)d_in[10];
    const float* coeff_W  = (const float*)d_in[11];
    const float* coeff_b  = (const float*)d_in[12];
    const float* bases    = (const float*)d_in[13];
    const float* sage_bias= (const float*)d_in[14];
    const float* ln_w     = (const float*)d_in[15];
    const float* ln_b     = (const float*)d_in[16];

    float* out = (float*)d_out;
    float* out_xa  = out;
    float* out_xb  = out + (size_t)N_NODES * NC;
    float* out_sf  = out + (size_t)2 * N_NODES * NC;
    float* out_ori = out_sf + NS * NH;

    float *p_mid_a, *p_mid_b, *p_raw_a, *p_raw_b, *p_xa, *p_xb, *p_Wab, *p_Wcat;
    cudaGetSymbolAddress((void**)&p_mid_a, g_mid_a);
    cudaGetSymbolAddress((void**)&p_mid_b, g_mid_b);
    cudaGetSymbolAddress((void**)&p_raw_a, g_raw_a);
    cudaGetSymbolAddress((void**)&p_raw_b, g_raw_b);
    cudaGetSymbolAddress((void**)&p_xa,    g_xa);
    cudaGetSymbolAddress((void**)&p_xb,    g_xb);
    cudaGetSymbolAddress((void**)&p_Wab,   g_Wab);
    cudaGetSymbolAddress((void**)&p_Wcat,  g_Wcat);

    // ---- CSR build (once per launch, reused by both layers) ----
    zero_deg_kernel<<<(3 * N_NODES + 255) / 256, 256>>>();
    hist_kernel<<<1024, 256>>>(e_ab, 0);
    hist_kernel<<<1024, 256>>>(e_ba, 1);
    hist_kernel<<<1024, 256>>>(e_aa, 2);
    scan_kernel<<<3, 1024>>>();
    fill_kernel<<<1024, 256>>>(e_ab, 0);
    fill_kernel<<<1024, 256>>>(e_ba, 1);
    fill_kernel<<<1024, 256>>>(e_aa, 2);

    // ---- schema + dynamic weights ----
    schema_kernel<<<1, 512>>>(schema_x, sei, pre_W, pre_b, gcn_W, gcn_b,
                              coeff_W, coeff_b, out_sf, out_ori);
    buildW_kernel<<<(2 * NC * NC + 255) / 256, 256>>>(bases);

    const int AGG_GRID  = (N_NODES * 32 + 255) / 256;
    const int GEMM_GRID = (N_NODES + 127) / 128;

    // ---- layer 0 ----
    agg_kernel<<<AGG_GRID, 256>>>(x_a, x_b, 0, p_mid_b, 128, 0);
    agg_kernel<<<AGG_GRID, 256>>>(x_b, x_a, 1, p_mid_a, 256, 0);
    agg_kernel<<<AGG_GRID, 256>>>(x_a, x_a, 2, p_mid_a, 256, 128);
    gemm_kernel<256><<<GEMM_GRID, 256>>>(p_mid_a, p_Wcat, p_raw_a);
    gemm_kernel<128><<<GEMM_GRID, 256>>>(p_mid_b, p_Wab, p_raw_b);
    ln_kernel<<<AGG_GRID, 256>>>(p_raw_a, sage_bias + 1 * NC, sage_bias + 2 * NC,
                                 ln_w + 0 * NC, ln_b + 0 * NC, p_xa);
    ln_kernel<<<AGG_GRID, 256>>>(p_raw_b, sage_bias + 0 * NC, nullptr,
                                 ln_w + 1 * NC, ln_b + 1 * NC, p_xb);

    // ---- layer 1 ----
    agg_kernel<<<AGG_GRID, 256>>>(p_xa, p_xb, 0, p_mid_b, 128, 0);
    agg_kernel<<<AGG_GRID, 256>>>(p_xb, p_xa, 1, p_mid_a, 256, 0);
    agg_kernel<<<AGG_GRID, 256>>>(p_xa, p_xa, 2, p_mid_a, 256, 128);
    gemm_kernel<256><<<GEMM_GRID, 256>>>(p_mid_a, p_Wcat + NC * 256, p_raw_a);
    gemm_kernel<128><<<GEMM_GRID, 256>>>(p_mid_b, p_Wab + NC * NC, p_raw_b);
    ln_kernel<<<AGG_GRID, 256>>>(p_raw_a, sage_bias + (3 + 1) * NC, sage_bias + (3 + 2) * NC,
                                 ln_w + 2 * NC, ln_b + 2 * NC, out_xa);
    ln_kernel<<<AGG_GRID, 256>>>(p_raw_b, sage_bias + (3 + 0) * NC, nullptr,
                                 ln_w + 3 * NC, ln_b + 3 * NC, out_xb);
}

// round 2
// speedup vs baseline: 1.5039x; 1.5039x over previous
#include <cuda_runtime.h>
#include <cstddef>

#define N_NODES 50000
#define NC 128
#define NE 800000
#define NS 8
#define NH 64
#define NB_ 8
#define LN_EPS 1e-5f

// ---------------- scratch (device globals; no allocation) ----------------
__device__ int   g_off [3][N_NODES + 1];
__device__ int   g_pos [3][N_NODES];       // doubles as degree histogram
__device__ int   g_srcs[3][NE];
__device__ float g_mid_a[(size_t)N_NODES * 256];
__device__ float g_mid_b[(size_t)N_NODES * NC];
__device__ float g_xa   [(size_t)N_NODES * NC];
__device__ float g_xb   [(size_t)N_NODES * NC];
__device__ float g_Wab [2][NC * NC];
__device__ float g_Wcat[2][NC * 256];   // [j][0:128]=W_ba  [j][128:256]=W_aa
__device__ float g_coeff[3][NB_];       // 0: ab, 1: ba, 2: aa

// ---------------- CSR build ----------------
__global__ void zero_deg_kernel() {
    int i = blockIdx.x * blockDim.x + threadIdx.x;
    if (i < 3 * N_NODES) ((int*)g_pos)[i] = 0;
}

__global__ void hist3_kernel(const int* __restrict__ e0, const int* __restrict__ e1,
                             const int* __restrict__ e2) {
    int i = blockIdx.x * blockDim.x + threadIdx.x;  // grid covers exactly 3*NE
    int t = i / NE, j = i % NE;
    const int* e = (t == 0) ? e0 : (t == 1) ? e1 : e2;
    atomicAdd(&g_pos[t][e[NE + j]], 1);
}

__global__ void scan_kernel() {
    int t = blockIdx.x;
    int* deg = g_pos[t];
    int* off = g_off[t];
    __shared__ int wsum[32];
    __shared__ int carry;
    int tid = threadIdx.x, lane = tid & 31, wid = tid >> 5;
    if (tid == 0) carry = 0;
    __syncthreads();
    for (int base = 0; base < N_NODES; base += 1024) {
        int i = base + tid;
        int v = (i < N_NODES) ? deg[i] : 0;
        int s = v;
#pragma unroll
        for (int d = 1; d < 32; d <<= 1) {
            int n = __shfl_up_sync(0xffffffffu, s, d);
            if (lane >= d) s += n;
        }
        if (lane == 31) wsum[wid] = s;
        __syncthreads();
        if (wid == 0) {
            int w = wsum[lane];
#pragma unroll
            for (int d = 1; d < 32; d <<= 1) {
                int n = __shfl_up_sync(0xffffffffu, w, d);
                if (lane >= d) w += n;
            }
            wsum[lane] = w;
        }
        __syncthreads();
        int c = carry;
        int excl = c + s - v + (wid ? wsum[wid - 1] : 0);
        if (i < N_NODES) { off[i] = excl; deg[i] = excl; }
        int tot = wsum[31];
        __syncthreads();
        if (tid == 0) carry = c + tot;
        __syncthreads();
    }
    if (threadIdx.x == 0) off[N_NODES] = carry;
}

__global__ void fill3_kernel(const int* __restrict__ e0, const int* __restrict__ e1,
                             const int* __restrict__ e2) {
    int i = blockIdx.x * blockDim.x + threadIdx.x;
    int t = i / NE, j = i % NE;
    const int* e = (t == 0) ? e0 : (t == 1) ? e1 : e2;
    int s = e[j], d = e[NE + j];
    int p = atomicAdd(&g_pos[t][d], 1);
    g_srcs[t][p] = s;
}

// ---------------- schema GCN + dynamic coefficients (1 block, 512 thr) ----------------
__global__ void schema_kernel(const float* __restrict__ schema_x, const int* __restrict__ sei,
                              const float* __restrict__ pre_W, const float* __restrict__ pre_b,
                              const float* __restrict__ gcn_W, const float* __restrict__ gcn_b,
                              const float* __restrict__ coeff_W, const float* __restrict__ coeff_b,
                              float* __restrict__ out_sf, float* __restrict__ out_ori) {
    __shared__ float h [NS][NH];
    __shared__ float xw[NS][NH];
    __shared__ float sf[NS][NH];
    __shared__ float dinv[NS];
    int tid = threadIdx.x;              // 512 = 8*64
    int s = tid / NH, j = tid % NH;

    float acc = pre_b[j];
    for (int i = 0; i < NH; i++) acc += schema_x[s * NH + i] * pre_W[j * NH + i];
    h[s][j] = acc;
    out_ori[s * NH + j] = acc;
    __syncthreads();

    float xacc = 0.f;
    for (int k = 0; k < NH; k++) xacc += h[s][k] * gcn_W[j * NH + k];
    xw[s][j] = xacc;
    if (tid < NS) {
        float d = 1.0f;                  // self loop
        for (int e = 0; e < 24; e++) if (sei[24 + e] == tid) d += 1.0f;
        dinv[tid] = rsqrtf(fmaxf(d, 1e-12f));
    }
    __syncthreads();

    float o = gcn_b[j] + dinv[s] * dinv[s] * xw[s][j];
    for (int e = 0; e < 24; e++) {
        int es = sei[e], ed = sei[24 + e];
        if (ed == s) o += dinv[es] * dinv[s] * xw[es][j];
    }
    o = fmaxf(o, 0.f);
    sf[s][j] = o;
    out_sf[s * NH + j] = o;
    __syncthreads();

    if (tid < 3 * NB_) {
        int t = tid / NB_, i = tid % NB_;
        int ssrc = (t == 1) ? 1 : 0;     // ab:(0,1) ba:(1,0) aa:(0,0)
        int sdst = (t == 0) ? 1 : 0;
        float c = coeff_b[i];
        for (int k = 0; k < NH; k++) c += sf[ssrc][k] * coeff_W[i * 128 + k];
        for (int k = 0; k < NH; k++) c += sf[sdst][k] * coeff_W[i * 128 + 64 + k];
        g_coeff[t][i] = c;
    }
}

__global__ void buildW_kernel(const float* __restrict__ bases) {
    int id = blockIdx.x * blockDim.x + threadIdx.x;
    if (id >= 2 * NC * NC) return;
    int l = id / (NC * NC);
    int jk = id % (NC * NC);
    int j = jk / NC, k = jk % NC;
    float wab = 0.f, wba = 0.f, waa = 0.f;
#pragma unroll
    for (int i = 0; i < NB_; i++) {
        float b = bases[(size_t)l * NB_ * NC * NC + (size_t)i * NC * NC + jk];
        wab += g_coeff[0][i] * b;
        wba += g_coeff[1][i] * b;
        waa += g_coeff[2][i] * b;
    }
    g_Wab[l][jk] = wab;
    g_Wcat[l][j * 256 + k] = wba;
    g_Wcat[l][j * 256 + 128 + k] = waa;
}

// ---------------- aggregation: warp per destination node ----------------
__device__ __forceinline__ void acc_range(const float* __restrict__ xsrc,
                                          const int* __restrict__ srcs,
                                          int beg, int end, int col, float4& out) {
    float4 a0 = make_float4(0, 0, 0, 0), a1 = a0;
    int e = beg;
    for (; e + 2 <= end; e += 2) {
        int s0 = srcs[e], s1 = srcs[e + 1];
        float4 v0 = *(const float4*)(xsrc + (size_t)s0 * NC + col);
        float4 v1 = *(const float4*)(xsrc + (size_t)s1 * NC + col);
        a0.x += v0.x; a0.y += v0.y; a0.z += v0.z; a0.w += v0.w;
        a1.x += v1.x; a1.y += v1.y; a1.z += v1.z; a1.w += v1.w;
    }
    if (e < end) {
        int s0 = srcs[e];
        float4 v0 = *(const float4*)(xsrc + (size_t)s0 * NC + col);
        a0.x += v0.x; a0.y += v0.y; a0.z += v0.z; a0.w += v0.w;
    }
    float inv = 1.0f / fmaxf((float)(end - beg), 1.0f);
    out.x = (a0.x + a1.x) * inv;
    out.y = (a0.y + a1.y) * inv;
    out.z = (a0.z + a1.z) * inv;
    out.w = (a0.w + a1.w) * inv;
}

// ab edges: src=x_a, dst=x_b -> mid_b [N,128]
__global__ void agg_b_kernel(const float* __restrict__ xa, const float* __restrict__ xb,
                             float* __restrict__ mid) {
    int g = blockIdx.x * blockDim.x + threadIdx.x;
    int node = g >> 5, lane = g & 31;
    if (node >= N_NODES) return;
    int col = lane * 4;
    float4 m;
    acc_range(xa, g_srcs[0], g_off[0][node], g_off[0][node + 1], col, m);
    float4 xd = *(const float4*)(xb + (size_t)node * NC + col);
    m.x += xd.x; m.y += xd.y; m.z += xd.z; m.w += xd.w;
    *(float4*)(mid + (size_t)node * NC + col) = m;
}

// ba (src=x_b) + aa (src=x_a) edges, dst=x_a -> mid_a [N,256]
__global__ void agg_a_kernel(const float* __restrict__ xa, const float* __restrict__ xb,
                             float* __restrict__ mid) {
    int g = blockIdx.x * blockDim.x + threadIdx.x;
    int node = g >> 5, lane = g & 31;
    if (node >= N_NODES) return;
    int col = lane * 4;
    float4 xd = *(const float4*)(xa + (size_t)node * NC + col);
    float4 m0, m1;
    acc_range(xb, g_srcs[1], g_off[1][node], g_off[1][node + 1], col, m0);
    acc_range(xa, g_srcs[2], g_off[2][node], g_off[2][node + 1], col, m1);
    m0.x += xd.x; m0.y += xd.y; m0.z += xd.z; m0.w += xd.w;
    m1.x += xd.x; m1.y += xd.y; m1.z += xd.z; m1.w += xd.w;
    *(float4*)(mid + (size_t)node * 256 + col) = m0;
    *(float4*)(mid + (size_t)node * 256 + 128 + col) = m1;
}

// ---------------- tf32 GEMM + bias + LayerNorm + ReLU fused ----------------
// out[M,128] = relu(LN(A[M,K] @ W[128,K]^T + b1 (+ b2)) * lw + lb)
__device__ __forceinline__ float tf32r(float x) {
    unsigned u;
    asm("cvt.rna.tf32.f32 %0, %1;" : "=r"(u) : "f"(x));
    return __uint_as_float(u);
}

#define APITCH 36
#define OPITCH 132

template <int K>
__global__ void __launch_bounds__(256)
gemm_ln_kernel(const float* __restrict__ A, const float* __restrict__ W,
               const float* __restrict__ b1, const float* __restrict__ b2,
               const float* __restrict__ lw, const float* __restrict__ lb,
               float* __restrict__ out, int M) {
    extern __shared__ float buf[];           // max(2*128*36, 128*132) = 16896 floats
    float* At = buf;                         // [128][36] (32 k cols used)
    float* Wt = buf + 128 * APITCH;          // [128][36]
    __shared__ float sb[3][NC];              // combined bias, lw, lb

    int tid = threadIdx.x;
    int lane = tid & 31, wid = tid >> 5;
    int warp_m = wid >> 2, warp_n = wid & 3; // 2 x 4 warps
    int gid = lane >> 2, tig = lane & 3;
    int row0 = blockIdx.x * 128;

    if (tid < NC) {
        float c = b1[tid];
        if (b2) c += b2[tid];
        sb[0][tid] = c;
        sb[1][tid] = lw[tid];
        sb[2][tid] = lb[tid];
    }

    float acc[4][4][4];
#pragma unroll
    for (int i = 0; i < 4; i++)
#pragma unroll
        for (int j = 0; j < 4; j++)
#pragma unroll
            for (int c = 0; c < 4; c++) acc[i][j][c] = 0.f;

    for (int kc = 0; kc < K; kc += 32) {
#pragma unroll
        for (int it = 0; it < 4; it++) {
            int idx = tid + it * 256;        // 0..1023
            int r = idx >> 3, seg = idx & 7;
            float4 v = make_float4(0, 0, 0, 0);
            if (row0 + r < M)
                v = *(const float4*)(A + (size_t)(row0 + r) * K + kc + seg * 4);
            float* dp = At + r * APITCH + seg * 4;
            dp[0] = tf32r(v.x); dp[1] = tf32r(v.y); dp[2] = tf32r(v.z); dp[3] = tf32r(v.w);
            float4 w4 = *(const float4*)(W + (size_t)r * K + kc + seg * 4);
            float* dw = Wt + r * APITCH + seg * 4;
            dw[0] = tf32r(w4.x); dw[1] = tf32r(w4.y); dw[2] = tf32r(w4.z); dw[3] = tf32r(w4.w);
        }
        __syncthreads();
#pragma unroll
        for (int ks = 0; ks < 4; ks++) {
            int k = ks * 8;
            unsigned bfr[4][2];
#pragma unroll
            for (int j = 0; j < 4; j++) {
                int n0 = warp_n * 32 + j * 8;
                bfr[j][0] = __float_as_uint(Wt[(n0 + gid) * APITCH + k + tig]);
                bfr[j][1] = __float_as_uint(Wt[(n0 + gid) * APITCH + k + tig + 4]);
            }
#pragma unroll
            for (int i = 0; i < 4; i++) {
                int m0 = warp_m * 64 + i * 16;
                unsigned a0 = __float_as_uint(At[(m0 + gid) * APITCH + k + tig]);
                unsigned a1 = __float_as_uint(At[(m0 + gid + 8) * APITCH + k + tig]);
                unsigned a2 = __float_as_uint(At[(m0 + gid) * APITCH + k + tig + 4]);
                unsigned a3 = __float_as_uint(At[(m0 + gid + 8) * APITCH + k + tig + 4]);
#pragma unroll
                for (int j = 0; j < 4; j++) {
                    asm volatile(
                        "mma.sync.aligned.m16n8k8.row.col.f32.tf32.tf32.f32 "
                        "{%0,%1,%2,%3}, {%4,%5,%6,%7}, {%8,%9}, {%0,%1,%2,%3};\n"
                        : "+f"(acc[i][j][0]), "+f"(acc[i][j][1]),
                          "+f"(acc[i][j][2]), "+f"(acc[i][j][3])
                        : "r"(a0), "r"(a1), "r"(a2), "r"(a3),
                          "r"(bfr[j][0]), "r"(bfr[j][1]));
                }
            }
        }
        __syncthreads();
    }

    // stage output tile (aliases At/Wt — safe after last syncthreads)
    float* Ot = buf;                         // [128][132]
#pragma unroll
    for (int i = 0; i < 4; i++) {
        int m0 = warp_m * 64 + i * 16;
#pragma unroll
        for (int j = 0; j < 4; j++) {
            int n0 = warp_n * 32 + j * 8 + 2 * tig;
            Ot[(m0 + gid) * OPITCH + n0]         = acc[i][j][0];
            Ot[(m0 + gid) * OPITCH + n0 + 1]     = acc[i][j][1];
            Ot[(m0 + gid + 8) * OPITCH + n0]     = acc[i][j][2];
            Ot[(m0 + gid + 8) * OPITCH + n0 + 1] = acc[i][j][3];
        }
    }
    __syncthreads();

    // block-local LayerNorm: warp wid handles rows wid*16 .. wid*16+15
    int col = lane * 4;
    for (int rr = 0; rr < 16; rr++) {
        int r = wid * 16 + rr;
        int grow = row0 + r;
        if (grow >= M) break;
        float4 v = *(const float4*)&Ot[r * OPITCH + col];
        v.x += sb[0][col];     v.y += sb[0][col + 1];
        v.z += sb[0][col + 2]; v.w += sb[0][col + 3];
        float s = v.x + v.y + v.z + v.w;
#pragma unroll
        for (int o = 16; o > 0; o >>= 1) s += __shfl_xor_sync(0xffffffffu, s, o);
        float mu = s * (1.0f / NC);
        float dx = v.x - mu, dy = v.y - mu, dz = v.z - mu, dw = v.w - mu;
        float q = dx * dx + dy * dy + dz * dz + dw * dw;
#pragma unroll
        for (int o = 16; o > 0; o >>= 1) q += __shfl_xor_sync(0xffffffffu, q, o);
        float rs = rsqrtf(q * (1.0f / NC) + LN_EPS);
        float4 y;
        y.x = fmaxf(dx * rs * sb[1][col]     + sb[2][col],     0.f);
        y.y = fmaxf(dy * rs * sb[1][col + 1] + sb[2][col + 1], 0.f);
        y.z = fmaxf(dz * rs * sb[1][col + 2] + sb[2][col + 2], 0.f);
        y.w = fmaxf(dw * rs * sb[1][col + 3] + sb[2][col + 3], 0.f);
        *(float4*)(out + (size_t)grow * NC + col) = y;
    }
}

// ---------------- launch ----------------
extern "C" void kernel_launch(void* const* d_in, const int* in_sizes, int n_in,
                              void* d_out, int out_size) {
    (void)in_sizes; (void)n_in; (void)out_size;
    const float* x_a      = (const float*)d_in[0];
    const float* x_b      = (const float*)d_in[1];
    const float* schema_x = (const float*)d_in[2];
    const int*   e_ab     = (const int*)d_in[3];
    const int*   e_ba     = (const int*)d_in[4];
    const int*   e_aa     = (const int*)d_in[5];
    const int*   sei      = (const int*)d_in[6];
    const float* pre_W    = (const float*)d_in[7];
    const float* pre_b    = (const float*)d_in[8];
    const float* gcn_W    = (const float*)d_in[9];
    const float* gcn_b    = (const float*)d_in[10];
    const float* coeff_W  = (const float*)d_in[11];
    const float* coeff_b  = (const float*)d_in[12];
    const float* bases    = (const float*)d_in[13];
    const float* sage_bias= (const float*)d_in[14];
    const float* ln_w     = (const float*)d_in[15];
    const float* ln_b     = (const float*)d_in[16];

    float* out = (float*)d_out;
    float* out_xa  = out;
    float* out_xb  = out + (size_t)N_NODES * NC;
    float* out_sf  = out + (size_t)2 * N_NODES * NC;
    float* out_ori = out_sf + NS * NH;

    float *p_mid_a, *p_mid_b, *p_xa, *p_xb, *p_Wab, *p_Wcat;
    cudaGetSymbolAddress((void**)&p_mid_a, g_mid_a);
    cudaGetSymbolAddress((void**)&p_mid_b, g_mid_b);
    cudaGetSymbolAddress((void**)&p_xa,    g_xa);
    cudaGetSymbolAddress((void**)&p_xb,    g_xb);
    cudaGetSymbolAddress((void**)&p_Wab,   g_Wab);
    cudaGetSymbolAddress((void**)&p_Wcat,  g_Wcat);

    const int SMEM_GEMM = 16896 * sizeof(float);
    cudaFuncSetAttribute(gemm_ln_kernel<256>,
                         cudaFuncAttributeMaxDynamicSharedMemorySize, SMEM_GEMM);
    cudaFuncSetAttribute(gemm_ln_kernel<128>,
                         cudaFuncAttributeMaxDynamicSharedMemorySize, SMEM_GEMM);

    // ---- CSR build ----
    zero_deg_kernel<<<(3 * N_NODES + 255) / 256, 256>>>();
    hist3_kernel<<<3 * NE / 256, 256>>>(e_ab, e_ba, e_aa);
    scan_kernel<<<3, 1024>>>();
    fill3_kernel<<<3 * NE / 256, 256>>>(e_ab, e_ba, e_aa);

    // ---- schema + dynamic weights ----
    schema_kernel<<<1, 512>>>(schema_x, sei, pre_W, pre_b, gcn_W, gcn_b,
                              coeff_W, coeff_b, out_sf, out_ori);
    buildW_kernel<<<(2 * NC * NC + 255) / 256, 256>>>(bases);

    const int AGG_GRID  = (N_NODES * 32 + 255) / 256;
    const int GEMM_GRID = (N_NODES + 127) / 128;

    // ---- layer 0 ----
    agg_b_kernel<<<AGG_GRID, 256>>>(x_a, x_b, p_mid_b);
    agg_a_kernel<<<AGG_GRID, 256>>>(x_a, x_b, p_mid_a);
    gemm_ln_kernel<256><<<GEMM_GRID, 256, SMEM_GEMM>>>(
        p_mid_a, p_Wcat[0] ? p_Wcat : p_Wcat, sage_bias + 1 * NC, sage_bias + 2 * NC,
        ln_w + 0 * NC, ln_b + 0 * NC, p_xa, N_NODES);
    gemm_ln_kernel<128><<<GEMM_GRID, 256, SMEM_GEMM>>>(
        p_mid_b, p_Wab, sage_bias + 0 * NC, nullptr,
        ln_w + 1 * NC, ln_b + 1 * NC, p_xb, N_NODES);

    // ---- layer 1 ----
    agg_b_kernel<<<AGG_GRID, 256>>>(p_xa, p_xb, p_mid_b);
    agg_a_kernel<<<AGG_GRID, 256>>>(p_xa, p_xb, p_mid_a);
    gemm_ln_kernel<256><<<GEMM_GRID, 256, SMEM_GEMM>>>(
        p_mid_a, p_Wcat + NC * 256, sage_bias + 4 * NC, sage_bias + 5 * NC,
        ln_w + 2 * NC, ln_b + 2 * NC, out_xa, N_NODES);
    gemm_ln_kernel<128><<<GEMM_GRID, 256, SMEM_GEMM>>>(
        p_mid_b, p_Wab + NC * NC, sage_bias + 3 * NC, nullptr,
        ln_w + 3 * NC, ln_b + 3 * NC, out_xb, N_NODES);
}